// round 14
// baseline (speedup 1.0000x reference)
#include <cuda_runtime.h>
#include <cuda_fp16.h>
#include <cstdint>

// Shapes: x [B,N,128] f32 | edge_index [2,E] i32 | edge_weight [B,E] f32
//         W [128,128] f32 | b [128] f32  ->  out [B,N,128] f32
#define DIM 128
#define CAP 128
#define TCTR 40032   // tile-counter slot inside g_cnt (targets are < 40000)

__device__ __half g_h2[10240256];              // fp16 h (fast path, B==2)
__device__ float4 g_listw[40000 * CAP + 16];   // {src, w0, w1, pad} per edge
__device__ int    g_cnt[40064];
// generic-path scratch
__device__ float  g_h[10240256];
__device__ int2   g_list[40000 * CAP];

// ---------------------------------------------------------------------------
// fp16 / mma helpers
// ---------------------------------------------------------------------------
__device__ __forceinline__ uint32_t f16x2_pack(float lo, float hi) {
    __half2 h = __floats2half2_rn(lo, hi);
    return *(uint32_t*)&h;
}
__device__ __forceinline__ void mma_f16(float* c, const uint32_t* a, const uint32_t* b) {
    asm volatile("mma.sync.aligned.m16n8k16.row.col.f32.f16.f16.f32 "
        "{%0,%1,%2,%3}, {%4,%5,%6,%7}, {%8,%9}, {%0,%1,%2,%3};"
        : "+f"(c[0]), "+f"(c[1]), "+f"(c[2]), "+f"(c[3])
        : "r"(a[0]), "r"(a[1]), "r"(a[2]), "r"(a[3]), "r"(b[0]), "r"(b[1]));
}
__device__ __forceinline__ void ldmatrix_x4(uint32_t* r, uint32_t smem_addr) {
    asm volatile("ldmatrix.sync.aligned.m8n8.x4.shared.b16 {%0,%1,%2,%3}, [%4];"
        : "=r"(r[0]), "=r"(r[1]), "=r"(r[2]), "=r"(r[3]) : "r"(smem_addr));
}

// ---------------------------------------------------------------------------
// Fused kernel (fast path, B==2): EVERY CTA stages W, builds a grid-strided
// slice of the {src,w0,w1} edge lists, then joins the persistent fp16 GEMM
// tile pool (64x128 tile, h -> fp16, atomic tile counter).
// 52 KB smem -> 3 CTAs/SM; single wave, no dedicated build blocks.
// Inner loop: per k16 step, 1 A-ldmatrix + 4 B-ldmatrix + 8 MMA.
// ---------------------------------------------------------------------------
#define P      68
#define XS_O   0
#define W0_O   (64 * P)
#define SMEM_U32 (192 * P)   // 13056 u32 = 52224 B

__global__ __launch_bounds__(256, 3) void fused_build_gemm_kernel(
    const float* __restrict__ x, const float* __restrict__ W,
    const float* __restrict__ bias, const int* __restrict__ ei,
    const float* __restrict__ ew, int E, int ntiles)
{
    const int tid = threadIdx.x;

    extern __shared__ uint32_t smu[];
    uint32_t* xs  = smu + XS_O;    // x fp16 pairs  [64 rows][P]
    uint32_t* w0s = smu + W0_O;    // W fp16 pairs  [128 n-rows][P]
    __shared__ int s_tile;

    // Stage W (fp16) once per CTA
    for (int idx = tid; idx < 128 * 32; idx += 256) {
        int o = idx >> 5, q = idx & 31;
        float4 v = __ldg((const float4*)W + idx);
        *(uint2*)&w0s[o * P + 2 * q] =
            make_uint2(f16x2_pack(v.x, v.y), f16x2_pack(v.z, v.w));
    }

    // Build slice: grid-strided over edges (all CTAs participate)
    {
        const int stride = gridDim.x * 256;
        for (int e = blockIdx.x * 256 + tid; e < E; e += stride) {
            int   src = __ldg(ei + e);
            int   tgt = __ldg(ei + E + e);
            float w0  = __ldg(ew + e);
            float w1  = __ldg(ew + E + e);
            int pos = atomicAdd(&g_cnt[tgt], 1);
            if (pos < CAP)
                g_listw[(size_t)tgt * CAP + pos] =
                    make_float4(__int_as_float(src), w0, w1, 0.0f);
        }
    }

    const int wid  = tid >> 5;
    const int lane = tid & 31;
    const int t    = lane & 3;
    const int wm   = wid >> 1;    // row block of 16
    const int wn   = wid & 1;     // col block of 64

    float2 brg[8];
    #pragma unroll
    for (int nb = 0; nb < 8; nb++) {
        int c0 = wn * 64 + nb * 8 + 2 * t;
        brg[nb].x = __ldg(bias + c0);
        brg[nb].y = __ldg(bias + c0 + 1);
    }

    // ldmatrix per-lane addresses (byte, shared space), fixed per warp.
    const uint32_t xs_sm = (uint32_t)__cvta_generic_to_shared(xs);
    const uint32_t w_sm  = (uint32_t)__cvta_generic_to_shared(w0s);
    const int m  = lane >> 3;
    const int r  = lane & 7;
    const int rbase = wm * 16;
    // A matrices: {m0-7/k0-7, m8-15/k0-7, m0-7/k8-15, m8-15/k8-15}
    const uint32_t a_addr0 = xs_sm +
        4u * ((rbase + (m & 1) * 8 + r) * P + (m >> 1) * 4);
    // B matrices for nb-pair p: {nb/kh0, nb/kh1, nb+1/kh0, nb+1/kh1}
    uint32_t b_addr0[4];
    #pragma unroll
    for (int p = 0; p < 4; p++)
        b_addr0[p] = w_sm +
            4u * ((wn * 64 + p * 16 + (m >> 1) * 8 + r) * P + (m & 1) * 4);

    const int g = lane >> 2;
    for (;;) {
        if (tid == 0) s_tile = atomicAdd(&g_cnt[TCTR], 1);
        __syncthreads();               // orders W/xs staging + s_tile for all
        const int tile = s_tile;
        if (tile >= ntiles) break;

        // Stage 64-row x tile as fp16 pairs
        const float* xtile = x + (size_t)tile * 64 * DIM;
        for (int idx = tid; idx < 64 * 32; idx += 256) {
            int row = idx >> 5, q = idx & 31;
            float4 v = __ldg((const float4*)(xtile + row * DIM) + q);
            *(uint2*)&xs[row * P + 2 * q] =
                make_uint2(f16x2_pack(v.x, v.y), f16x2_pack(v.z, v.w));
        }
        __syncthreads();

        float c[8][4];
        #pragma unroll
        for (int nb = 0; nb < 8; nb++)
            #pragma unroll
            for (int i = 0; i < 4; i++) c[nb][i] = 0.0f;

        #pragma unroll
        for (int ks = 0; ks < 8; ks++) {
            uint32_t a[4];
            ldmatrix_x4(a, a_addr0 + ks * 32u);
            #pragma unroll
            for (int p = 0; p < 4; p++) {
                uint32_t bb[4];
                ldmatrix_x4(bb, b_addr0[p] + ks * 32u);
                mma_f16(c[2 * p],     a, bb);
                mma_f16(c[2 * p + 1], a, bb + 2);
            }
        }

        // Epilogue: +bias, convert to fp16, store
        const size_t row0 = (size_t)tile * 64 + rbase;
        #pragma unroll
        for (int nb = 0; nb < 8; nb++) {
            int col0 = wn * 64 + nb * 8 + 2 * t;
            size_t ra = row0 + g;
            __half2 v0 = __floats2half2_rn(c[nb][0] + brg[nb].x, c[nb][1] + brg[nb].y);
            __half2 v1 = __floats2half2_rn(c[nb][2] + brg[nb].x, c[nb][3] + brg[nb].y);
            *(__half2*)(g_h2 + ra * DIM + col0)       = v0;
            *(__half2*)(g_h2 + (ra + 8) * DIM + col0) = v1;
        }
    }
}

// ---------------------------------------------------------------------------
// Gather (fast path, B==2): one warp per node, both batches. Lane l owns
// features [4l, 4l+4) per batch. Single 16B broadcast per edge. Loop shape is
// the measured optimum — only change: force <=32 regs for 64-warp occupancy.
// ---------------------------------------------------------------------------
__global__ __launch_bounds__(128, 16) void gather_h2_kernel(
    float* __restrict__ out, int N)
{
    int n = blockIdx.x * 4 + (threadIdx.x >> 5);
    if (n >= N) return;
    const int lane = threadIdx.x & 31;

    int cnt = g_cnt[n];
    if (cnt > CAP) cnt = CAP;
    const float4* lw = g_listw + (size_t)n * CAP;
    const __half* h0p = g_h2;
    const __half* h1p = g_h2 + (size_t)N * DIM;

    float4 a0 = make_float4(0.f, 0.f, 0.f, 0.f);
    float4 a1 = make_float4(0.f, 0.f, 0.f, 0.f);

    for (int j = 0; j < cnt; j++) {
        float4 le = __ldg(lw + j);                 // {src, w0, w1, _} broadcast
        int s = __float_as_int(le.x);
        uint2 v0 = __ldg((const uint2*)(h0p + (size_t)s * DIM) + lane);
        uint2 v1 = __ldg((const uint2*)(h1p + (size_t)s * DIM) + lane);
        float2 f00 = __half22float2(*(__half2*)&v0.x);
        float2 f01 = __half22float2(*(__half2*)&v0.y);
        float2 f10 = __half22float2(*(__half2*)&v1.x);
        float2 f11 = __half22float2(*(__half2*)&v1.y);
        a0.x += le.y * f00.x; a0.y += le.y * f00.y;
        a0.z += le.y * f01.x; a0.w += le.y * f01.y;
        a1.x += le.z * f10.x; a1.y += le.z * f10.y;
        a1.z += le.z * f11.x; a1.w += le.z * f11.y;
    }

    *((float4*)(out + (size_t)n * DIM) + lane)       = a0;
    *((float4*)(out + ((size_t)N + n) * DIM) + lane) = a1;
}

// ---------------------------------------------------------------------------
// Generic path (any B / row count): fp32 h, int2 lists
// ---------------------------------------------------------------------------
__global__ void build_list_kernel(const int* __restrict__ ei, int E) {
    int e = blockIdx.x * blockDim.x + threadIdx.x;
    if (e >= E) return;
    int src = __ldg(ei + e);
    int tgt = __ldg(ei + E + e);
    int pos = atomicAdd(&g_cnt[tgt], 1);
    if (pos < CAP) g_list[(size_t)tgt * CAP + pos] = make_int2(src, e);
}

__global__ __launch_bounds__(256) void gemm_bias_kernel(
    const float* __restrict__ x, const float* __restrict__ W,
    const float* __restrict__ bias, int total_rows)
{
    extern __shared__ float sm[];
    float* Wt = sm;
    float* xs = sm + 128 * 129;
    const int tid = threadIdx.x;
    for (int idx = tid; idx < DIM * DIM; idx += 256) {
        int o = idx >> 7, k = idx & 127;
        Wt[k * 129 + o] = W[idx];
    }
    const int o = tid & 127;
    const int rg = tid >> 7;
    const float bo = bias[o];
    __syncthreads();
    const int nchunks = (total_rows + 7) >> 3;
    for (int c = blockIdx.x; c < nchunks; c += gridDim.x) {
        const int base = c * 8;
        for (int idx = tid; idx < 8 * DIM; idx += 256) {
            int r = base + (idx >> 7);
            xs[idx] = (r < total_rows) ? x[(size_t)r * DIM + (idx & 127)] : 0.0f;
        }
        __syncthreads();
        const float* xr = xs + rg * 4 * DIM;
        float a0 = 0.f, a1 = 0.f, a2 = 0.f, a3 = 0.f;
        #pragma unroll
        for (int k = 0; k < DIM; k += 4) {
            float4 x0 = *(const float4*)(xr + 0 * DIM + k);
            float4 x1 = *(const float4*)(xr + 1 * DIM + k);
            float4 x2 = *(const float4*)(xr + 2 * DIM + k);
            float4 x3 = *(const float4*)(xr + 3 * DIM + k);
            float w0 = Wt[(k + 0) * 129 + o], w1 = Wt[(k + 1) * 129 + o];
            float w2 = Wt[(k + 2) * 129 + o], w3 = Wt[(k + 3) * 129 + o];
            a0 += x0.x * w0; a1 += x1.x * w0; a2 += x2.x * w0; a3 += x3.x * w0;
            a0 += x0.y * w1; a1 += x1.y * w1; a2 += x2.y * w1; a3 += x3.y * w1;
            a0 += x0.z * w2; a1 += x1.z * w2; a2 += x2.z * w2; a3 += x3.z * w2;
            a0 += x0.w * w3; a1 += x1.w * w3; a2 += x2.w * w3; a3 += x3.w * w3;
        }
        const int r0 = base + rg * 4;
        if (r0 + 0 < total_rows) g_h[(size_t)(r0 + 0) * DIM + o] = a0 + bo;
        if (r0 + 1 < total_rows) g_h[(size_t)(r0 + 1) * DIM + o] = a1 + bo;
        if (r0 + 2 < total_rows) g_h[(size_t)(r0 + 2) * DIM + o] = a2 + bo;
        if (r0 + 3 < total_rows) g_h[(size_t)(r0 + 3) * DIM + o] = a3 + bo;
        __syncthreads();
    }
}

__global__ __launch_bounds__(256) void gather_generic_kernel(
    const float* __restrict__ ew, float* __restrict__ out, int E, int N, int B)
{
    int n = blockIdx.x * (blockDim.x >> 5) + (threadIdx.x >> 5);
    if (n >= N) return;
    const int lane = threadIdx.x & 31;
    int cnt = g_cnt[n];
    if (cnt > CAP) cnt = CAP;
    const int2* lst = g_list + (size_t)n * CAP;
    for (int b = 0; b < B; b++) {
        float4 a = make_float4(0.f, 0.f, 0.f, 0.f);
        for (int j = 0; j < cnt; j++) {
            int2 le = __ldg(lst + j);
            float w = __ldg(ew + (size_t)b * E + le.y);
            float4 v = *((const float4*)(g_h + ((size_t)b * N + le.x) * DIM) + lane);
            a.x += w * v.x; a.y += w * v.y; a.z += w * v.z; a.w += w * v.w;
        }
        *((float4*)(out + ((size_t)b * N + n) * DIM) + lane) = a;
    }
}

// ---------------------------------------------------------------------------
extern "C" void kernel_launch(void* const* d_in, const int* in_sizes, int n_in,
                              void* d_out, int out_size)
{
    const float* x  = (const float*)d_in[0];
    const int*   ei = (const int*)  d_in[1];
    const float* ew = (const float*)d_in[2];
    const float* W  = (const float*)d_in[3];
    const float* b  = (const float*)d_in[4];
    float* out = (float*)d_out;

    const int E          = in_sizes[1] / 2;
    const int B          = in_sizes[2] / E;
    const int total_rows = in_sizes[0] / DIM;
    const int N          = total_rows / B;

    void* cnt_ptr = nullptr;
    cudaGetSymbolAddress(&cnt_ptr, g_cnt);
    cudaMemsetAsync(cnt_ptr, 0, sizeof(int) * 40064, 0);

    if (((total_rows & 127) == 0) && B == 2) {
        const size_t smem = SMEM_U32 * sizeof(uint32_t);   // 52 KB -> 3 CTAs/SM
        cudaFuncSetAttribute(fused_build_gemm_kernel,
                             cudaFuncAttributeMaxDynamicSharedMemorySize, (int)smem);
        int ntiles = total_rows / 64;
        int gworkers = ntiles < 444 ? ntiles : 444;
        fused_build_gemm_kernel<<<gworkers, 256, smem>>>(x, W, b, ei, ew, E, ntiles);

        gather_h2_kernel<<<(N + 3) / 4, 128>>>(out, N);
    } else {
        build_list_kernel<<<(E + 255) / 256, 256>>>(ei, E);
        const size_t smem = (size_t)(128 * 129 + 8 * DIM) * sizeof(float);
        cudaFuncSetAttribute(gemm_bias_kernel,
                             cudaFuncAttributeMaxDynamicSharedMemorySize, (int)smem);
        gemm_bias_kernel<<<296, 256, smem>>>(x, W, b, total_rows);
        int blocks = (N + 7) / 8;
        gather_generic_kernel<<<blocks, 256>>>(ew, out, E, N, B);
    }
}

// round 15
// speedup vs baseline: 1.1250x; 1.1250x over previous
#include <cuda_runtime.h>
#include <cuda_fp16.h>
#include <cstdint>

// Shapes: x [B,N,128] f32 | edge_index [2,E] i32 | edge_weight [B,E] f32
//         W [128,128] f32 | b [128] f32  ->  out [B,N,128] f32
#define DIM 128
#define CAP 128
#define TCTR 40032   // tile-counter slot inside g_cnt (targets are < 40000)

__device__ __half g_h2[10240256];              // fp16 h (fast path, B==2)
__device__ float4 g_listw[40000 * CAP + 16];   // {src, w0, w1, pad} per edge
__device__ int    g_cnt[40064];
// generic-path scratch
__device__ float  g_h[10240256];
__device__ int2   g_list[40000 * CAP];

// ---------------------------------------------------------------------------
// fp16 / mma helpers
// ---------------------------------------------------------------------------
__device__ __forceinline__ uint32_t f16x2_pack(float lo, float hi) {
    __half2 h = __floats2half2_rn(lo, hi);
    return *(uint32_t*)&h;
}
__device__ __forceinline__ void mma_f16(float* c, const uint32_t* a, const uint32_t* b) {
    asm volatile("mma.sync.aligned.m16n8k16.row.col.f32.f16.f16.f32 "
        "{%0,%1,%2,%3}, {%4,%5,%6,%7}, {%8,%9}, {%0,%1,%2,%3};"
        : "+f"(c[0]), "+f"(c[1]), "+f"(c[2]), "+f"(c[3])
        : "r"(a[0]), "r"(a[1]), "r"(a[2]), "r"(a[3]), "r"(b[0]), "r"(b[1]));
}
__device__ __forceinline__ void ldmatrix_x4(uint32_t* r, uint32_t smem_addr) {
    asm volatile("ldmatrix.sync.aligned.m8n8.x4.shared.b16 {%0,%1,%2,%3}, [%4];"
        : "=r"(r[0]), "=r"(r[1]), "=r"(r[2]), "=r"(r[3]) : "r"(smem_addr));
}

// ---------------------------------------------------------------------------
// Fused kernel (fast path, B==2): EVERY CTA stages W, builds a grid-strided
// slice of the {src,w0,w1} edge lists, then joins the persistent fp16 GEMM
// tile pool (64x128 tile, h -> fp16, atomic tile counter).
// 52 KB smem -> 3 CTAs/SM; single wave, no dedicated build blocks.
// Inner loop: per k16 step, 1 A-ldmatrix + 4 B-ldmatrix + 8 MMA.
// ---------------------------------------------------------------------------
#define P      68
#define XS_O   0
#define W0_O   (64 * P)
#define SMEM_U32 (192 * P)   // 13056 u32 = 52224 B

__global__ __launch_bounds__(256, 3) void fused_build_gemm_kernel(
    const float* __restrict__ x, const float* __restrict__ W,
    const float* __restrict__ bias, const int* __restrict__ ei,
    const float* __restrict__ ew, int E, int ntiles)
{
    const int tid = threadIdx.x;

    extern __shared__ uint32_t smu[];
    uint32_t* xs  = smu + XS_O;    // x fp16 pairs  [64 rows][P]
    uint32_t* w0s = smu + W0_O;    // W fp16 pairs  [128 n-rows][P]
    __shared__ int s_tile;

    // Stage W (fp16) once per CTA
    for (int idx = tid; idx < 128 * 32; idx += 256) {
        int o = idx >> 5, q = idx & 31;
        float4 v = __ldg((const float4*)W + idx);
        *(uint2*)&w0s[o * P + 2 * q] =
            make_uint2(f16x2_pack(v.x, v.y), f16x2_pack(v.z, v.w));
    }

    // Build slice: grid-strided over edges (all CTAs participate)
    {
        const int stride = gridDim.x * 256;
        for (int e = blockIdx.x * 256 + tid; e < E; e += stride) {
            int   src = __ldg(ei + e);
            int   tgt = __ldg(ei + E + e);
            float w0  = __ldg(ew + e);
            float w1  = __ldg(ew + E + e);
            int pos = atomicAdd(&g_cnt[tgt], 1);
            if (pos < CAP)
                g_listw[(size_t)tgt * CAP + pos] =
                    make_float4(__int_as_float(src), w0, w1, 0.0f);
        }
    }

    const int wid  = tid >> 5;
    const int lane = tid & 31;
    const int t    = lane & 3;
    const int wm   = wid >> 1;    // row block of 16
    const int wn   = wid & 1;     // col block of 64

    float2 brg[8];
    #pragma unroll
    for (int nb = 0; nb < 8; nb++) {
        int c0 = wn * 64 + nb * 8 + 2 * t;
        brg[nb].x = __ldg(bias + c0);
        brg[nb].y = __ldg(bias + c0 + 1);
    }

    // ldmatrix per-lane addresses (byte, shared space), fixed per warp.
    const uint32_t xs_sm = (uint32_t)__cvta_generic_to_shared(xs);
    const uint32_t w_sm  = (uint32_t)__cvta_generic_to_shared(w0s);
    const int m  = lane >> 3;
    const int r  = lane & 7;
    const int rbase = wm * 16;
    // A matrices: {m0-7/k0-7, m8-15/k0-7, m0-7/k8-15, m8-15/k8-15}
    const uint32_t a_addr0 = xs_sm +
        4u * ((rbase + (m & 1) * 8 + r) * P + (m >> 1) * 4);
    // B matrices for nb-pair p: {nb/kh0, nb/kh1, nb+1/kh0, nb+1/kh1}
    uint32_t b_addr0[4];
    #pragma unroll
    for (int p = 0; p < 4; p++)
        b_addr0[p] = w_sm +
            4u * ((wn * 64 + p * 16 + (m >> 1) * 8 + r) * P + (m & 1) * 4);

    const int g = lane >> 2;
    for (;;) {
        if (tid == 0) s_tile = atomicAdd(&g_cnt[TCTR], 1);
        __syncthreads();               // orders W/xs staging + s_tile for all
        const int tile = s_tile;
        if (tile >= ntiles) break;

        // Stage 64-row x tile as fp16 pairs
        const float* xtile = x + (size_t)tile * 64 * DIM;
        for (int idx = tid; idx < 64 * 32; idx += 256) {
            int row = idx >> 5, q = idx & 31;
            float4 v = __ldg((const float4*)(xtile + row * DIM) + q);
            *(uint2*)&xs[row * P + 2 * q] =
                make_uint2(f16x2_pack(v.x, v.y), f16x2_pack(v.z, v.w));
        }
        __syncthreads();

        float c[8][4];
        #pragma unroll
        for (int nb = 0; nb < 8; nb++)
            #pragma unroll
            for (int i = 0; i < 4; i++) c[nb][i] = 0.0f;

        #pragma unroll
        for (int ks = 0; ks < 8; ks++) {
            uint32_t a[4];
            ldmatrix_x4(a, a_addr0 + ks * 32u);
            #pragma unroll
            for (int p = 0; p < 4; p++) {
                uint32_t bb[4];
                ldmatrix_x4(bb, b_addr0[p] + ks * 32u);
                mma_f16(c[2 * p],     a, bb);
                mma_f16(c[2 * p + 1], a, bb + 2);
            }
        }

        // Epilogue: +bias, convert to fp16, store
        const size_t row0 = (size_t)tile * 64 + rbase;
        #pragma unroll
        for (int nb = 0; nb < 8; nb++) {
            int col0 = wn * 64 + nb * 8 + 2 * t;
            size_t ra = row0 + g;
            __half2 v0 = __floats2half2_rn(c[nb][0] + brg[nb].x, c[nb][1] + brg[nb].y);
            __half2 v1 = __floats2half2_rn(c[nb][2] + brg[nb].x, c[nb][3] + brg[nb].y);
            *(__half2*)(g_h2 + ra * DIM + col0)       = v0;
            *(__half2*)(g_h2 + (ra + 8) * DIM + col0) = v1;
        }
    }
}

// ---------------------------------------------------------------------------
// Gather (fast path, B==2): one warp per node, both batches. Lane l owns
// features [4l, 4l+4) per batch. Single 16B broadcast per edge.
// Measured-best shape (45.5-45.8 us over three runs); FROZEN — no reg cap,
// no unrolling, no warp splitting.
// ---------------------------------------------------------------------------
__global__ __launch_bounds__(128) void gather_h2_kernel(
    float* __restrict__ out, int N)
{
    int n = blockIdx.x * 4 + (threadIdx.x >> 5);
    if (n >= N) return;
    const int lane = threadIdx.x & 31;

    int cnt = g_cnt[n];
    if (cnt > CAP) cnt = CAP;
    const float4* lw = g_listw + (size_t)n * CAP;
    const __half* h0p = g_h2;
    const __half* h1p = g_h2 + (size_t)N * DIM;

    float4 a0 = make_float4(0.f, 0.f, 0.f, 0.f);
    float4 a1 = make_float4(0.f, 0.f, 0.f, 0.f);

    for (int j = 0; j < cnt; j++) {
        float4 le = __ldg(lw + j);                 // {src, w0, w1, _} broadcast
        int s = __float_as_int(le.x);
        uint2 v0 = __ldg((const uint2*)(h0p + (size_t)s * DIM) + lane);
        uint2 v1 = __ldg((const uint2*)(h1p + (size_t)s * DIM) + lane);
        float2 f00 = __half22float2(*(__half2*)&v0.x);
        float2 f01 = __half22float2(*(__half2*)&v0.y);
        float2 f10 = __half22float2(*(__half2*)&v1.x);
        float2 f11 = __half22float2(*(__half2*)&v1.y);
        a0.x += le.y * f00.x; a0.y += le.y * f00.y;
        a0.z += le.y * f01.x; a0.w += le.y * f01.y;
        a1.x += le.z * f10.x; a1.y += le.z * f10.y;
        a1.z += le.z * f11.x; a1.w += le.z * f11.y;
    }

    *((float4*)(out + (size_t)n * DIM) + lane)       = a0;
    *((float4*)(out + ((size_t)N + n) * DIM) + lane) = a1;
}

// ---------------------------------------------------------------------------
// Generic path (any B / row count): fp32 h, int2 lists
// ---------------------------------------------------------------------------
__global__ void build_list_kernel(const int* __restrict__ ei, int E) {
    int e = blockIdx.x * blockDim.x + threadIdx.x;
    if (e >= E) return;
    int src = __ldg(ei + e);
    int tgt = __ldg(ei + E + e);
    int pos = atomicAdd(&g_cnt[tgt], 1);
    if (pos < CAP) g_list[(size_t)tgt * CAP + pos] = make_int2(src, e);
}

__global__ __launch_bounds__(256) void gemm_bias_kernel(
    const float* __restrict__ x, const float* __restrict__ W,
    const float* __restrict__ bias, int total_rows)
{
    extern __shared__ float sm[];
    float* Wt = sm;
    float* xs = sm + 128 * 129;
    const int tid = threadIdx.x;
    for (int idx = tid; idx < DIM * DIM; idx += 256) {
        int o = idx >> 7, k = idx & 127;
        Wt[k * 129 + o] = W[idx];
    }
    const int o = tid & 127;
    const int rg = tid >> 7;
    const float bo = bias[o];
    __syncthreads();
    const int nchunks = (total_rows + 7) >> 3;
    for (int c = blockIdx.x; c < nchunks; c += gridDim.x) {
        const int base = c * 8;
        for (int idx = tid; idx < 8 * DIM; idx += 256) {
            int r = base + (idx >> 7);
            xs[idx] = (r < total_rows) ? x[(size_t)r * DIM + (idx & 127)] : 0.0f;
        }
        __syncthreads();
        const float* xr = xs + rg * 4 * DIM;
        float a0 = 0.f, a1 = 0.f, a2 = 0.f, a3 = 0.f;
        #pragma unroll
        for (int k = 0; k < DIM; k += 4) {
            float4 x0 = *(const float4*)(xr + 0 * DIM + k);
            float4 x1 = *(const float4*)(xr + 1 * DIM + k);
            float4 x2 = *(const float4*)(xr + 2 * DIM + k);
            float4 x3 = *(const float4*)(xr + 3 * DIM + k);
            float w0 = Wt[(k + 0) * 129 + o], w1 = Wt[(k + 1) * 129 + o];
            float w2 = Wt[(k + 2) * 129 + o], w3 = Wt[(k + 3) * 129 + o];
            a0 += x0.x * w0; a1 += x1.x * w0; a2 += x2.x * w0; a3 += x3.x * w0;
            a0 += x0.y * w1; a1 += x1.y * w1; a2 += x2.y * w1; a3 += x3.y * w1;
            a0 += x0.z * w2; a1 += x1.z * w2; a2 += x2.z * w2; a3 += x3.z * w2;
            a0 += x0.w * w3; a1 += x1.w * w3; a2 += x2.w * w3; a3 += x3.w * w3;
        }
        const int r0 = base + rg * 4;
        if (r0 + 0 < total_rows) g_h[(size_t)(r0 + 0) * DIM + o] = a0 + bo;
        if (r0 + 1 < total_rows) g_h[(size_t)(r0 + 1) * DIM + o] = a1 + bo;
        if (r0 + 2 < total_rows) g_h[(size_t)(r0 + 2) * DIM + o] = a2 + bo;
        if (r0 + 3 < total_rows) g_h[(size_t)(r0 + 3) * DIM + o] = a3 + bo;
        __syncthreads();
    }
}

__global__ __launch_bounds__(256) void gather_generic_kernel(
    const float* __restrict__ ew, float* __restrict__ out, int E, int N, int B)
{
    int n = blockIdx.x * (blockDim.x >> 5) + (threadIdx.x >> 5);
    if (n >= N) return;
    const int lane = threadIdx.x & 31;
    int cnt = g_cnt[n];
    if (cnt > CAP) cnt = CAP;
    const int2* lst = g_list + (size_t)n * CAP;
    for (int b = 0; b < B; b++) {
        float4 a = make_float4(0.f, 0.f, 0.f, 0.f);
        for (int j = 0; j < cnt; j++) {
            int2 le = __ldg(lst + j);
            float w = __ldg(ew + (size_t)b * E + le.y);
            float4 v = *((const float4*)(g_h + ((size_t)b * N + le.x) * DIM) + lane);
            a.x += w * v.x; a.y += w * v.y; a.z += w * v.z; a.w += w * v.w;
        }
        *((float4*)(out + ((size_t)b * N + n) * DIM) + lane) = a;
    }
}

// ---------------------------------------------------------------------------
extern "C" void kernel_launch(void* const* d_in, const int* in_sizes, int n_in,
                              void* d_out, int out_size)
{
    const float* x  = (const float*)d_in[0];
    const int*   ei = (const int*)  d_in[1];
    const float* ew = (const float*)d_in[2];
    const float* W  = (const float*)d_in[3];
    const float* b  = (const float*)d_in[4];
    float* out = (float*)d_out;

    const int E          = in_sizes[1] / 2;
    const int B          = in_sizes[2] / E;
    const int total_rows = in_sizes[0] / DIM;
    const int N          = total_rows / B;

    void* cnt_ptr = nullptr;
    cudaGetSymbolAddress(&cnt_ptr, g_cnt);
    cudaMemsetAsync(cnt_ptr, 0, sizeof(int) * 40064, 0);

    if (((total_rows & 127) == 0) && B == 2) {
        const size_t smem = SMEM_U32 * sizeof(uint32_t);   // 52 KB -> 3 CTAs/SM
        cudaFuncSetAttribute(fused_build_gemm_kernel,
                             cudaFuncAttributeMaxDynamicSharedMemorySize, (int)smem);
        int ntiles = total_rows / 64;
        int gworkers = ntiles < 444 ? ntiles : 444;
        fused_build_gemm_kernel<<<gworkers, 256, smem>>>(x, W, b, ei, ew, E, ntiles);

        gather_h2_kernel<<<(N + 3) / 4, 128>>>(out, N);
    } else {
        build_list_kernel<<<(E + 255) / 256, 256>>>(ei, E);
        const size_t smem = (size_t)(128 * 129 + 8 * DIM) * sizeof(float);
        cudaFuncSetAttribute(gemm_bias_kernel,
                             cudaFuncAttributeMaxDynamicSharedMemorySize, (int)smem);
        gemm_bias_kernel<<<296, 256, smem>>>(x, W, b, total_rows);
        int blocks = (N + 7) / 8;
        gather_generic_kernel<<<blocks, 256>>>(ew, out, E, N, B);
    }
}